// round 11
// baseline (speedup 1.0000x reference)
#include <cuda_runtime.h>
#include <cuda_bf16.h>
#include <math.h>
#include <stdint.h>

#define Bb 64
#define Tt 12
#define Nn 512
#define Dd 2
#define NB (Nn*Bb)   // 32768 rows (row = node*64 + batch)

// ---------------- device scratch ----------------
__device__ float g_h[2][NB*64];          // ping-pong hidden state
__device__ float g_s[NB*64];             // s = A^T h
// B fragments: [split][ktile 8][nw 4][lane 32][jpair 16] (j=tile/2, reg pairs)
__device__ uint32_t g_Bp[2*8*4*512];
__device__ float g_cvec[192];            // b_msg @ W_ih_m^T
__device__ float g_Wx[384];              // x weights [d][o]
__device__ float g_csum[Nn];
__device__ int   g_colj[Nn*Nn];
__device__ float g_colw[Nn*Nn];
__device__ int   g_cnt[Nn];

__device__ __forceinline__ uint32_t packbf(__nv_bfloat16 lo, __nv_bfloat16 hi) {
    return ((uint32_t)__bfloat16_as_ushort(hi) << 16) | (uint32_t)__bfloat16_as_ushort(lo);
}
__device__ __forceinline__ void split2(float v, __nv_bfloat16& b1, __nv_bfloat16& b2) {
    b1 = __float2bfloat16_rn(v);
    b2 = __float2bfloat16_rn(v - __bfloat162float(b1));
}

#define MMA16816(c, a, b) \
    asm volatile("mma.sync.aligned.m16n8k16.row.col.f32.bf16.bf16.f32 " \
        "{%0,%1,%2,%3}, {%4,%5,%6,%7}, {%8,%9}, {%0,%1,%2,%3};" \
        : "+f"((c)[0]), "+f"((c)[1]), "+f"((c)[2]), "+f"((c)[3]) \
        : "r"((a)[0]), "r"((a)[1]), "r"((a)[2]), "r"((a)[3]), \
          "r"((b)[0]), "r"((b)[1]))

// ---------------- prep: pack B fragments + tables ----------------
__global__ void prep_kernel(const float* __restrict__ W_hh,
                            const float* __restrict__ W_ih,
                            const float* __restrict__ W_msg,
                            const float* __restrict__ b_msg) {
    int idx = blockIdx.x * 256 + threadIdx.x;
    if (idx < 16384) {                      // (n 0..255) x (kpair 0..63)
        int n = idx >> 6, kp = idx & 63;
        int p = n >> 6, g = n & 63;
        float w[2];
        #pragma unroll
        for (int u = 0; u < 2; u++) {
            int k = 2*kp + u;
            float v = 0.f;
            if (k < 64) {
                if (p < 3) v = W_hh[(p*64 + g)*64 + k];
            } else {
                int ks = k - 64;
                if (p != 2) {
                    int o = (p == 3) ? (128 + g) : (p*64 + g);
                    float s = 0.f;
                    for (int m = 0; m < 64; m++) s += W_msg[m*64 + ks] * W_ih[o*66 + m];
                    v = s;
                }
            }
            w[u] = v;
        }
        __nv_bfloat16 lo1, lo2, hi1, hi2;
        split2(w[0], lo1, lo2);
        split2(w[1], hi1, hi2);
        int nt = n >> 3, kt = kp >> 3, q = kp & 7;
        int lane = ((n & 7) << 2) + (q & 3);
        int reg = q >> 2;
        int j = nt >> 2, nw = nt & 3;
        int loc = ((kt*4 + nw) << 9) + lane*16 + j*2 + reg;
        g_Bp[loc]          = packbf(lo1, hi1);
        g_Bp[16384 + loc]  = packbf(lo2, hi2);
    } else if (idx < 16384 + 384) {          // Wx[d][o]
        int j = idx - 16384;
        int d = j / 192, o = j - d*192;
        g_Wx[j] = W_ih[o*66 + 64 + d];
    } else if (idx < 16384 + 384 + 192) {    // cvec
        int o = idx - 16384 - 384;
        float s = 0.f;
        for (int m = 0; m < 64; m++) s += b_msg[m] * W_ih[o*66 + m];
        g_cvec[o] = s;
    }
}

// ---------------- deterministic CSC build + column sums (zero-padded to 64) --
__global__ void build_csc(const float* __restrict__ adj) {
    int i = blockIdx.x;
    int j = threadIdx.x;
    if (j < 64) { g_colj[i*Nn + j] = 0; g_colw[i*Nn + j] = 0.f; }
    float w = adj[j*Nn + i];
    bool p = (w > 0.f);
    unsigned mask = __ballot_sync(0xffffffffu, p);
    int warp = j >> 5, lane = j & 31;
    __shared__ int wcnt[16];
    __shared__ int wofs[16];
    __shared__ float ws[512];
    ws[j] = p ? w : 0.f;
    if (lane == 0) wcnt[warp] = __popc(mask);
    __syncthreads();
    if (j == 0) {
        int s = 0;
        for (int t = 0; t < 16; t++) { wofs[t] = s; s += wcnt[t]; }
        g_cnt[i] = s;
    }
    for (int stride = 256; stride > 0; stride >>= 1) {
        __syncthreads();
        if (j < stride) ws[j] += ws[j + stride];
    }
    if (j == 0) g_csum[i] = ws[0];
    __syncthreads();
    if (p) {
        int pos = wofs[warp] + __popc(mask & ((1u << lane) - 1u));
        g_colj[i*Nn + pos] = j;
        g_colw[i*Nn + pos] = w;
    }
}

// ---------------- per step kernel 1: s = A^T h ----------------
// grid 512 = (b:64) x (mc:2) x (iq:4); warp handles 16 columns; padded-64
// branchless edge blocks (exact: padding adds 0.0). 3 blocks/SM resident.
__global__ __launch_bounds__(256, 3)
void agg_kernel(const float* __restrict__ h0, int t) {
    extern __shared__ float hS[];   // [512][32]
    const float* __restrict__ hsrc = (t == 0) ? h0 : g_h[t & 1];
    int bid = blockIdx.x;
    int b = bid & 63, mc = (bid >> 6) & 1, iq = bid >> 7;
    int tid = threadIdx.x;

    for (int idx = tid; idx < Nn*8; idx += 256) {
        int j = idx >> 3, q = idx & 7;
        ((float4*)hS)[idx] = *(const float4*)(hsrc + (((j << 6) + b) << 6) + (mc << 5) + (q << 2));
    }
    __syncthreads();

    int lane = tid & 31, wid = tid >> 5;
    #pragma unroll 1
    for (int c = 0; c < 16; c++) {
        int i = (iq << 7) + (c << 3) + wid;
        int cnt = g_cnt[i];
        const int*   cj = g_colj + i*Nn;
        const float* cw = g_colw + i*Nn;
        float a0=0.f,a1=0.f,a2=0.f,a3=0.f,a4=0.f,a5=0.f,a6=0.f,a7=0.f;
        #pragma unroll
        for (int u = 0; u < 4; u++) {
            int e = u*8;
            int4   j0 = *(const int4*)(cj + e);
            int4   j1 = *(const int4*)(cj + e + 4);
            float4 w0 = *(const float4*)(cw + e);
            float4 w1 = *(const float4*)(cw + e + 4);
            a0 += w0.x * hS[(j0.x << 5) + lane];
            a1 += w0.y * hS[(j0.y << 5) + lane];
            a2 += w0.z * hS[(j0.z << 5) + lane];
            a3 += w0.w * hS[(j0.w << 5) + lane];
            a4 += w1.x * hS[(j1.x << 5) + lane];
            a5 += w1.y * hS[(j1.y << 5) + lane];
            a6 += w1.z * hS[(j1.z << 5) + lane];
            a7 += w1.w * hS[(j1.w << 5) + lane];
        }
        if (cnt > 32) {
            #pragma unroll
            for (int u = 4; u < 8; u++) {
                int e = u*8;
                int4   j0 = *(const int4*)(cj + e);
                int4   j1 = *(const int4*)(cj + e + 4);
                float4 w0 = *(const float4*)(cw + e);
                float4 w1 = *(const float4*)(cw + e + 4);
                a0 += w0.x * hS[(j0.x << 5) + lane];
                a1 += w0.y * hS[(j0.y << 5) + lane];
                a2 += w0.z * hS[(j0.z << 5) + lane];
                a3 += w0.w * hS[(j0.w << 5) + lane];
                a4 += w1.x * hS[(j1.x << 5) + lane];
                a5 += w1.y * hS[(j1.y << 5) + lane];
                a6 += w1.z * hS[(j1.z << 5) + lane];
                a7 += w1.w * hS[(j1.w << 5) + lane];
            }
            for (int e = 64; e < cnt; e++)
                a0 += cw[e] * hS[(cj[e] << 5) + lane];
        }
        g_s[(((i << 6) + b) << 6) + (mc << 5) + lane] =
            ((a0 + a1) + (a2 + a3)) + ((a4 + a5) + (a6 + a7));
    }
}

// ---------------- per step kernel 2: HMMA GEMM + in-register GRU epilogue ----
// grid 512 (node n = 64 rows); 256 threads = 8 warps = (mw:2) x (nw:4).
// Warp's N-tiles strided (nt = 4j+nw) -> all 4 planes in-register epilogue.
// B loads: 4 LDG.128 per split per batch (repacked layout), double-buffered.
__global__ __launch_bounds__(256, 2)
void gru_mma_kernel(const float* __restrict__ inputs,
                    const float* __restrict__ b_ih,
                    const float* __restrict__ b_hh,
                    const float* __restrict__ h0,
                    int t) {
    extern __shared__ char smc[];
    float* tb = (float*)smc;                       // 960 floats
    uint32_t* apack = (uint32_t*)(smc + 3840);     // [s][mt4][kt8][lane32][reg4] = 32KB

    const float* __restrict__ hsrc = (t == 0) ? h0 : g_h[t & 1];
    float* __restrict__ hdst = g_h[(t + 1) & 1];

    int n = blockIdx.x;
    int rowBase = n << 6;
    int tid = threadIdx.x;

    // tables
    for (int idx = tid; idx < 960; idx += 256) {
        float v = (idx < 192) ? b_ih[idx]
                : (idx < 384) ? b_hh[idx - 192]
                : (idx < 576) ? g_cvec[idx - 384]
                : g_Wx[idx - 576];
        tb[idx] = v;
    }
    // A staging: split [h|s] rows into 2 bf16 components, pack fragment layout
    for (int it = 0; it < 16; it++) {
        int item = tid + it*256;            // (r 0..63) x (kp 0..63)
        int r = item >> 6, kp = item & 63;
        int rowg = rowBase + r;
        const float* src = (kp < 32) ? (hsrc + rowg*64 + 2*kp)
                                     : (g_s + rowg*64 + 2*kp - 64);
        float2 v = *(const float2*)src;
        __nv_bfloat16 lo1, lo2, hi1, hi2;
        split2(v.x, lo1, lo2);
        split2(v.y, hi1, hi2);
        int mt = r >> 4, kt = kp >> 3, q = kp & 7;
        int lane = ((r & 7) << 2) + (q & 3);
        int reg = ((q >> 2) << 1) + ((r & 15) >> 3);
        apack[((0*4 + mt)*8 + kt)*128 + lane*4 + reg] = packbf(lo1, hi1);
        apack[((1*4 + mt)*8 + kt)*128 + lane*4 + reg] = packbf(lo2, hi2);
    }
    __syncthreads();

    int lane = tid & 31;
    int w = tid >> 5;
    int mw = w & 1, nw = w >> 1;

    float c[2][8][4];
    #pragma unroll
    for (int i = 0; i < 2; i++)
        #pragma unroll
        for (int j = 0; j < 8; j++)
            #pragma unroll
            for (int q = 0; q < 4; q++) c[i][j][q] = 0.f;

    const uint32_t* __restrict__ Bp = g_Bp;
    uint32_t bbuf[2][8][2];

    // preload batch 0 (sb=0, kt=0)
    {
        const uint4* bp = (const uint4*)(Bp + ((0*4 + nw) << 9) + lane*16);
        #pragma unroll
        for (int q = 0; q < 4; q++) {
            uint4 v = bp[q];
            bbuf[0][q*2 + 0][0] = v.x; bbuf[0][q*2 + 0][1] = v.y;
            bbuf[0][q*2 + 1][0] = v.z; bbuf[0][q*2 + 1][1] = v.w;
        }
    }
    // combos: 0=A1B1, 1=A2B1, 2=A1B2
    #pragma unroll 2
    for (int bi = 0; bi < 24; bi++) {
        int par = bi & 1;
        if (bi < 23) {
            int bn = bi + 1;
            int cn = bn >> 3, ktn = bn & 7;
            int sbn = (cn == 2) ? 1 : 0;
            const uint4* bp = (const uint4*)(Bp + (((sbn*8 + ktn)*4 + nw) << 9) + lane*16);
            #pragma unroll
            for (int q = 0; q < 4; q++) {
                uint4 v = bp[q];
                bbuf[par ^ 1][q*2 + 0][0] = v.x; bbuf[par ^ 1][q*2 + 0][1] = v.y;
                bbuf[par ^ 1][q*2 + 1][0] = v.z; bbuf[par ^ 1][q*2 + 1][1] = v.w;
            }
        }
        int combo = bi >> 3, kt = bi & 7;
        int sa = (combo == 1) ? 1 : 0;
        uint32_t a[2][4];
        #pragma unroll
        for (int mt2 = 0; mt2 < 2; mt2++)
            *(uint4*)a[mt2] = *(const uint4*)(apack +
                ((sa*4 + mw*2 + mt2)*8 + kt)*128 + lane*4);
        #pragma unroll
        for (int j = 0; j < 8; j++) {
            MMA16816(c[0][j], a[0], bbuf[par][j]);
            MMA16816(c[1][j], a[1], bbuf[par][j]);
        }
    }

    // ---- in-register GRU epilogue ----
    float cs = g_csum[n];
    int g4 = lane >> 2, tg = lane & 3;
    #pragma unroll
    for (int mt2 = 0; mt2 < 2; mt2++) {
        #pragma unroll
        for (int qh = 0; qh < 2; qh++) {
            int row = mw*32 + mt2*16 + g4 + 8*qh;   // batch index b = row
            int rowg = rowBase + row;
            const float* xp = inputs + ((row*Tt + t)*Nn + n)*Dd;
            float x0 = xp[0], x1 = xp[1];
            #pragma unroll
            for (int jg = 0; jg < 2; jg++) {
                int g0 = jg*32 + nw*8 + tg*2;        // plane-local gate index
                float2 hold = *(const float2*)(hsrc + rowg*64 + g0);
                float hn[2];
                #pragma unroll
                for (int u = 0; u < 2; u++) {
                    int g = g0 + u;
                    int q = qh*2 + u;
                    float vr  = c[mt2][0*2 + jg][q] + tb[g]       + tb[192 + g]
                              + cs*tb[384 + g] + x0*tb[576 + g] + x1*tb[768 + g];
                    float vz  = c[mt2][1*2 + jg][q] + tb[64 + g]  + tb[256 + g]
                              + cs*tb[448 + g] + x0*tb[640 + g] + x1*tb[832 + g];
                    float vnh = c[mt2][2*2 + jg][q] + tb[320 + g];
                    float vns = c[mt2][3*2 + jg][q] + tb[128 + g]
                              + cs*tb[512 + g] + x0*tb[704 + g] + x1*tb[896 + g];
                    float rg = 1.f / (1.f + expf(-vr));
                    float zg = 1.f / (1.f + expf(-vz));
                    float nn = tanhf(vns + rg*vnh);
                    hn[u] = (1.f - zg)*nn + zg*((u == 0) ? hold.x : hold.y);
                }
                *(float2*)(hdst + rowg*64 + g0) = make_float2(hn[0], hn[1]);
            }
        }
    }
}

// ---------------- final readout ----------------
__global__ void out_kernel(const float* __restrict__ W_out,
                           const float* __restrict__ b_out,
                           float* __restrict__ out) {
    __shared__ float wo[12*64];
    __shared__ float bo[12];
    int tid = threadIdx.x;
    for (int idx = tid; idx < 768; idx += 256) wo[idx] = W_out[idx];
    if (tid < 12) bo[tid] = b_out[tid];
    __syncthreads();
    int row = blockIdx.x * 256 + tid;
    float accs[12];
    #pragma unroll
    for (int hh = 0; hh < 12; hh++) accs[hh] = bo[hh];
    for (int k = 0; k < 64; k++) {
        float hv = g_h[0][row*64 + k];
        #pragma unroll
        for (int hh = 0; hh < 12; hh++) accs[hh] += hv * wo[hh*64 + k];
    }
    int n = row >> 6, b = row & 63;
    #pragma unroll
    for (int hh = 0; hh < 12; hh++)
        out[(b*12 + hh)*512 + n] = accs[hh];
}

extern "C" void kernel_launch(void* const* d_in, const int* in_sizes, int n_in,
                              void* d_out, int out_size) {
    const float* inputs = (const float*)d_in[0];
    const float* h0     = (const float*)d_in[1];
    const float* adj    = (const float*)d_in[2];
    const float* W_msg  = (const float*)d_in[3];
    const float* b_msg  = (const float*)d_in[4];
    const float* W_ih   = (const float*)d_in[5];
    const float* W_hh   = (const float*)d_in[6];
    const float* b_ih   = (const float*)d_in[7];
    const float* b_hh   = (const float*)d_in[8];
    const float* W_out  = (const float*)d_in[9];
    const float* b_out  = (const float*)d_in[10];
    float* out = (float*)d_out;

    static const int MMA_SMEM = 3840 + 32768;   // 36608 B
    cudaFuncSetAttribute(gru_mma_kernel, cudaFuncAttributeMaxDynamicSharedMemorySize, MMA_SMEM);
    cudaFuncSetAttribute(agg_kernel,     cudaFuncAttributeMaxDynamicSharedMemorySize, 65536);

    prep_kernel<<<67, 256>>>(W_hh, W_ih, W_msg, b_msg);
    build_csc<<<512, 512>>>(adj);

    // t=11 writes g_h[0]; out_kernel reads g_h[0].
    for (int t = 0; t < Tt; t++) {
        agg_kernel<<<512, 256, 65536>>>(h0, t);
        gru_mma_kernel<<<512, 256, MMA_SMEM>>>(inputs, b_ih, b_hh, h0, t);
    }
    out_kernel<<<128, 256>>>(W_out, b_out, out);
}

// round 12
// speedup vs baseline: 1.2355x; 1.2355x over previous
#include <cuda_runtime.h>
#include <cuda_bf16.h>
#include <math.h>
#include <stdint.h>

#define Bb 64
#define Tt 12
#define Nn 512
#define Dd 2
#define NB (Nn*Bb)   // 32768 rows (row = node*64 + batch)

// ---------------- device scratch ----------------
__device__ float g_h[2][NB*64];          // ping-pong hidden state
__device__ float g_s[NB*64];             // s = A^T h
// B fragments (round-10 layout): [split][ktile 8][ntile 32][lane 32][reg 2]
__device__ uint32_t g_Bp[2*8*32*64];
__device__ float g_cvec[192];            // b_msg @ W_ih_m^T
__device__ float g_Wx[384];              // x weights [d][o]
__device__ float g_csum[Nn];
__device__ int   g_colj[Nn*Nn];
__device__ float g_colw[Nn*Nn];
__device__ int   g_cnt[Nn];

__device__ __forceinline__ uint32_t packbf(__nv_bfloat16 lo, __nv_bfloat16 hi) {
    return ((uint32_t)__bfloat16_as_ushort(hi) << 16) | (uint32_t)__bfloat16_as_ushort(lo);
}
__device__ __forceinline__ void split2(float v, __nv_bfloat16& b1, __nv_bfloat16& b2) {
    b1 = __float2bfloat16_rn(v);
    b2 = __float2bfloat16_rn(v - __bfloat162float(b1));
}

#define MMA16816(c, a, b) \
    asm volatile("mma.sync.aligned.m16n8k16.row.col.f32.bf16.bf16.f32 " \
        "{%0,%1,%2,%3}, {%4,%5,%6,%7}, {%8,%9}, {%0,%1,%2,%3};" \
        : "+f"((c)[0]), "+f"((c)[1]), "+f"((c)[2]), "+f"((c)[3]) \
        : "r"((a)[0]), "r"((a)[1]), "r"((a)[2]), "r"((a)[3]), \
          "r"((b)[0]), "r"((b)[1]))

// ---------------- prep: pack B fragments + tables (round-10 layout) ---------
__global__ void prep_kernel(const float* __restrict__ W_hh,
                            const float* __restrict__ W_ih,
                            const float* __restrict__ W_msg,
                            const float* __restrict__ b_msg) {
    int idx = blockIdx.x * 256 + threadIdx.x;
    if (idx < 16384) {                      // (n 0..255) x (kpair 0..63)
        int n = idx >> 6, kp = idx & 63;
        int p = n >> 6, g = n & 63;
        float w[2];
        #pragma unroll
        for (int u = 0; u < 2; u++) {
            int k = 2*kp + u;
            float v = 0.f;
            if (k < 64) {
                if (p < 3) v = W_hh[(p*64 + g)*64 + k];
            } else {
                int ks = k - 64;
                if (p != 2) {
                    int o = (p == 3) ? (128 + g) : (p*64 + g);
                    float s = 0.f;
                    for (int m = 0; m < 64; m++) s += W_msg[m*64 + ks] * W_ih[o*66 + m];
                    v = s;
                }
            }
            w[u] = v;
        }
        __nv_bfloat16 lo1, lo2, hi1, hi2;
        split2(w[0], lo1, lo2);
        split2(w[1], hi1, hi2);
        int nt = n >> 3, kt = kp >> 3, q = kp & 7;
        int lane = ((n & 7) << 2) + (q & 3);
        int reg = q >> 2;
        g_Bp[((0*8 + kt)*32 + nt)*64 + lane*2 + reg] = packbf(lo1, hi1);
        g_Bp[((1*8 + kt)*32 + nt)*64 + lane*2 + reg] = packbf(lo2, hi2);
    } else if (idx < 16384 + 384) {          // Wx[d][o]
        int j = idx - 16384;
        int d = j / 192, o = j - d*192;
        g_Wx[j] = W_ih[o*66 + 64 + d];
    } else if (idx < 16384 + 384 + 192) {    // cvec
        int o = idx - 16384 - 384;
        float s = 0.f;
        for (int m = 0; m < 64; m++) s += b_msg[m] * W_ih[o*66 + m];
        g_cvec[o] = s;
    }
}

// ---------------- deterministic CSC build + column sums (zero-padded to 64) --
__global__ void build_csc(const float* __restrict__ adj) {
    int i = blockIdx.x;
    int j = threadIdx.x;
    if (j < 64) { g_colj[i*Nn + j] = 0; g_colw[i*Nn + j] = 0.f; }
    float w = adj[j*Nn + i];
    bool p = (w > 0.f);
    unsigned mask = __ballot_sync(0xffffffffu, p);
    int warp = j >> 5, lane = j & 31;
    __shared__ int wcnt[16];
    __shared__ int wofs[16];
    __shared__ float ws[512];
    ws[j] = p ? w : 0.f;
    if (lane == 0) wcnt[warp] = __popc(mask);
    __syncthreads();
    if (j == 0) {
        int s = 0;
        for (int t = 0; t < 16; t++) { wofs[t] = s; s += wcnt[t]; }
        g_cnt[i] = s;
    }
    for (int stride = 256; stride > 0; stride >>= 1) {
        __syncthreads();
        if (j < stride) ws[j] += ws[j + stride];
    }
    if (j == 0) g_csum[i] = ws[0];
    __syncthreads();
    if (p) {
        int pos = wofs[warp] + __popc(mask & ((1u << lane) - 1u));
        g_colj[i*Nn + pos] = j;
        g_colw[i*Nn + pos] = w;
    }
}

// ---------------- per step kernel 1: s = A^T h (L1-direct, float2 lanes) ----
// grid 256 = (bp:32) x (mc:2) x (cq:4); no smem. Warp owns a column; lane =
// (bsub = lane>>4, r-pair = lane&15): one float2 LDG per edge -> 2 FMAs.
// Per-block h working set = h[:, b-pair, r-half] = 128KB (L1-resident).
__global__ __launch_bounds__(256)
void agg_kernel(const float* __restrict__ h0, int t) {
    const float* __restrict__ hsrc = (t == 0) ? h0 : g_h[t & 1];
    int bid = blockIdx.x;
    int bp = bid & 31, mc = (bid >> 5) & 1, cq = bid >> 6;
    int tid = threadIdx.x;
    int lane = tid & 31, wid = tid >> 5;
    int bsub = lane >> 4;
    int b = (bp << 1) + bsub;
    int roff = (mc << 5) + ((lane & 15) << 1);

    #pragma unroll 1
    for (int c = 0; c < 16; c++) {
        int i = (cq << 7) + (c << 3) + wid;
        int cnt = g_cnt[i];
        const int*   cj = g_colj + i*Nn;
        const float* cw = g_colw + i*Nn;
        float2 a0 = {0.f,0.f}, a1 = {0.f,0.f}, a2 = {0.f,0.f}, a3 = {0.f,0.f};
        float2 a4 = {0.f,0.f}, a5 = {0.f,0.f}, a6 = {0.f,0.f}, a7 = {0.f,0.f};
        #pragma unroll
        for (int u = 0; u < 4; u++) {
            int e = u*8;
            int4   j0 = *(const int4*)(cj + e);
            int4   j1 = *(const int4*)(cj + e + 4);
            float4 w0 = *(const float4*)(cw + e);
            float4 w1 = *(const float4*)(cw + e + 4);
            float2 h0v = *(const float2*)(hsrc + (((j0.x << 6) + b) << 6) + roff);
            float2 h1v = *(const float2*)(hsrc + (((j0.y << 6) + b) << 6) + roff);
            float2 h2v = *(const float2*)(hsrc + (((j0.z << 6) + b) << 6) + roff);
            float2 h3v = *(const float2*)(hsrc + (((j0.w << 6) + b) << 6) + roff);
            float2 h4v = *(const float2*)(hsrc + (((j1.x << 6) + b) << 6) + roff);
            float2 h5v = *(const float2*)(hsrc + (((j1.y << 6) + b) << 6) + roff);
            float2 h6v = *(const float2*)(hsrc + (((j1.z << 6) + b) << 6) + roff);
            float2 h7v = *(const float2*)(hsrc + (((j1.w << 6) + b) << 6) + roff);
            a0.x += w0.x*h0v.x; a0.y += w0.x*h0v.y;
            a1.x += w0.y*h1v.x; a1.y += w0.y*h1v.y;
            a2.x += w0.z*h2v.x; a2.y += w0.z*h2v.y;
            a3.x += w0.w*h3v.x; a3.y += w0.w*h3v.y;
            a4.x += w1.x*h4v.x; a4.y += w1.x*h4v.y;
            a5.x += w1.y*h5v.x; a5.y += w1.y*h5v.y;
            a6.x += w1.z*h6v.x; a6.y += w1.z*h6v.y;
            a7.x += w1.w*h7v.x; a7.y += w1.w*h7v.y;
        }
        if (cnt > 32) {
            #pragma unroll
            for (int u = 4; u < 8; u++) {
                int e = u*8;
                int4   j0 = *(const int4*)(cj + e);
                int4   j1 = *(const int4*)(cj + e + 4);
                float4 w0 = *(const float4*)(cw + e);
                float4 w1 = *(const float4*)(cw + e + 4);
                float2 h0v = *(const float2*)(hsrc + (((j0.x << 6) + b) << 6) + roff);
                float2 h1v = *(const float2*)(hsrc + (((j0.y << 6) + b) << 6) + roff);
                float2 h2v = *(const float2*)(hsrc + (((j0.z << 6) + b) << 6) + roff);
                float2 h3v = *(const float2*)(hsrc + (((j0.w << 6) + b) << 6) + roff);
                float2 h4v = *(const float2*)(hsrc + (((j1.x << 6) + b) << 6) + roff);
                float2 h5v = *(const float2*)(hsrc + (((j1.y << 6) + b) << 6) + roff);
                float2 h6v = *(const float2*)(hsrc + (((j1.z << 6) + b) << 6) + roff);
                float2 h7v = *(const float2*)(hsrc + (((j1.w << 6) + b) << 6) + roff);
                a0.x += w0.x*h0v.x; a0.y += w0.x*h0v.y;
                a1.x += w0.y*h1v.x; a1.y += w0.y*h1v.y;
                a2.x += w0.z*h2v.x; a2.y += w0.z*h2v.y;
                a3.x += w0.w*h3v.x; a3.y += w0.w*h3v.y;
                a4.x += w1.x*h4v.x; a4.y += w1.x*h4v.y;
                a5.x += w1.y*h5v.x; a5.y += w1.y*h5v.y;
                a6.x += w1.z*h6v.x; a6.y += w1.z*h6v.y;
                a7.x += w1.w*h7v.x; a7.y += w1.w*h7v.y;
            }
            for (int e = 64; e < cnt; e++) {
                float2 hv = *(const float2*)(hsrc + (((cj[e] << 6) + b) << 6) + roff);
                a0.x += cw[e]*hv.x; a0.y += cw[e]*hv.y;
            }
        }
        float2 r;
        r.x = ((a0.x + a1.x) + (a2.x + a3.x)) + ((a4.x + a5.x) + (a6.x + a7.x));
        r.y = ((a0.y + a1.y) + (a2.y + a3.y)) + ((a4.y + a5.y) + (a6.y + a7.y));
        *(float2*)(g_s + (((i << 6) + b) << 6) + roff) = r;
    }
}

// ---------------- per step kernel 2: HMMA GEMM + in-register GRU epilogue ----
// (exact round-10 version: strided N-tiles, uint2 B loads, double-buffered)
__global__ __launch_bounds__(256, 2)
void gru_mma_kernel(const float* __restrict__ inputs,
                    const float* __restrict__ b_ih,
                    const float* __restrict__ b_hh,
                    const float* __restrict__ h0,
                    int t) {
    extern __shared__ char smc[];
    float* tb = (float*)smc;                       // 960 floats
    uint32_t* apack = (uint32_t*)(smc + 3840);     // [s][mt4][kt8][lane32][reg4] = 32KB

    const float* __restrict__ hsrc = (t == 0) ? h0 : g_h[t & 1];
    float* __restrict__ hdst = g_h[(t + 1) & 1];

    int n = blockIdx.x;
    int rowBase = n << 6;
    int tid = threadIdx.x;

    for (int idx = tid; idx < 960; idx += 256) {
        float v = (idx < 192) ? b_ih[idx]
                : (idx < 384) ? b_hh[idx - 192]
                : (idx < 576) ? g_cvec[idx - 384]
                : g_Wx[idx - 576];
        tb[idx] = v;
    }
    for (int it = 0; it < 16; it++) {
        int item = tid + it*256;            // (r 0..63) x (kp 0..63)
        int r = item >> 6, kp = item & 63;
        int rowg = rowBase + r;
        const float* src = (kp < 32) ? (hsrc + rowg*64 + 2*kp)
                                     : (g_s + rowg*64 + 2*kp - 64);
        float2 v = *(const float2*)src;
        __nv_bfloat16 lo1, lo2, hi1, hi2;
        split2(v.x, lo1, lo2);
        split2(v.y, hi1, hi2);
        int mt = r >> 4, kt = kp >> 3, q = kp & 7;
        int lane = ((r & 7) << 2) + (q & 3);
        int reg = ((q >> 2) << 1) + ((r & 15) >> 3);
        apack[((0*4 + mt)*8 + kt)*128 + lane*4 + reg] = packbf(lo1, hi1);
        apack[((1*4 + mt)*8 + kt)*128 + lane*4 + reg] = packbf(lo2, hi2);
    }
    __syncthreads();

    int lane = tid & 31;
    int w = tid >> 5;
    int mw = w & 1, nw = w >> 1;

    float c[2][8][4];
    #pragma unroll
    for (int i = 0; i < 2; i++)
        #pragma unroll
        for (int j = 0; j < 8; j++)
            #pragma unroll
            for (int q = 0; q < 4; q++) c[i][j][q] = 0.f;

    const uint32_t* __restrict__ Bp = g_Bp;
    uint32_t bbuf[2][8][2];
    {
        const uint32_t* bp = Bp + lane*2;
        #pragma unroll
        for (int j = 0; j < 8; j++)
            *(uint2*)bbuf[0][j] = *(const uint2*)(bp + (4*j + nw)*64);
    }
    #pragma unroll 2
    for (int bi = 0; bi < 24; bi++) {
        int par = bi & 1;
        if (bi < 23) {
            int bn = bi + 1;
            int cn = bn >> 3, ktn = bn & 7;
            int sbn = (cn == 2) ? 1 : 0;
            const uint32_t* bp = Bp + ((sbn*8 + ktn)*32)*64 + lane*2;
            #pragma unroll
            for (int j = 0; j < 8; j++)
                *(uint2*)bbuf[par ^ 1][j] = *(const uint2*)(bp + (4*j + nw)*64);
        }
        int combo = bi >> 3, kt = bi & 7;
        int sa = (combo == 1) ? 1 : 0;
        uint32_t a[2][4];
        #pragma unroll
        for (int mt2 = 0; mt2 < 2; mt2++)
            *(uint4*)a[mt2] = *(const uint4*)(apack +
                ((sa*4 + mw*2 + mt2)*8 + kt)*128 + lane*4);
        #pragma unroll
        for (int j = 0; j < 8; j++) {
            MMA16816(c[0][j], a[0], bbuf[par][j]);
            MMA16816(c[1][j], a[1], bbuf[par][j]);
        }
    }

    float cs = g_csum[n];
    int g4 = lane >> 2, tg = lane & 3;
    #pragma unroll
    for (int mt2 = 0; mt2 < 2; mt2++) {
        #pragma unroll
        for (int qh = 0; qh < 2; qh++) {
            int row = mw*32 + mt2*16 + g4 + 8*qh;
            int rowg = rowBase + row;
            const float* xp = inputs + ((row*Tt + t)*Nn + n)*Dd;
            float x0 = xp[0], x1 = xp[1];
            #pragma unroll
            for (int jg = 0; jg < 2; jg++) {
                int g0 = jg*32 + nw*8 + tg*2;
                float2 hold = *(const float2*)(hsrc + rowg*64 + g0);
                float hn[2];
                #pragma unroll
                for (int u = 0; u < 2; u++) {
                    int g = g0 + u;
                    int q = qh*2 + u;
                    float vr  = c[mt2][0*2 + jg][q] + tb[g]       + tb[192 + g]
                              + cs*tb[384 + g] + x0*tb[576 + g] + x1*tb[768 + g];
                    float vz  = c[mt2][1*2 + jg][q] + tb[64 + g]  + tb[256 + g]
                              + cs*tb[448 + g] + x0*tb[640 + g] + x1*tb[832 + g];
                    float vnh = c[mt2][2*2 + jg][q] + tb[320 + g];
                    float vns = c[mt2][3*2 + jg][q] + tb[128 + g]
                              + cs*tb[512 + g] + x0*tb[704 + g] + x1*tb[896 + g];
                    float rg = 1.f / (1.f + expf(-vr));
                    float zg = 1.f / (1.f + expf(-vz));
                    float nn = tanhf(vns + rg*vnh);
                    hn[u] = (1.f - zg)*nn + zg*((u == 0) ? hold.x : hold.y);
                }
                *(float2*)(hdst + rowg*64 + g0) = make_float2(hn[0], hn[1]);
            }
        }
    }
}

// ---------------- final readout ----------------
__global__ void out_kernel(const float* __restrict__ W_out,
                           const float* __restrict__ b_out,
                           float* __restrict__ out) {
    __shared__ float wo[12*64];
    __shared__ float bo[12];
    int tid = threadIdx.x;
    for (int idx = tid; idx < 768; idx += 256) wo[idx] = W_out[idx];
    if (tid < 12) bo[tid] = b_out[tid];
    __syncthreads();
    int row = blockIdx.x * 256 + tid;
    float accs[12];
    #pragma unroll
    for (int hh = 0; hh < 12; hh++) accs[hh] = bo[hh];
    for (int k = 0; k < 64; k++) {
        float hv = g_h[0][row*64 + k];
        #pragma unroll
        for (int hh = 0; hh < 12; hh++) accs[hh] += hv * wo[hh*64 + k];
    }
    int n = row >> 6, b = row & 63;
    #pragma unroll
    for (int hh = 0; hh < 12; hh++)
        out[(b*12 + hh)*512 + n] = accs[hh];
}

extern "C" void kernel_launch(void* const* d_in, const int* in_sizes, int n_in,
                              void* d_out, int out_size) {
    const float* inputs = (const float*)d_in[0];
    const float* h0     = (const float*)d_in[1];
    const float* adj    = (const float*)d_in[2];
    const float* W_msg  = (const float*)d_in[3];
    const float* b_msg  = (const float*)d_in[4];
    const float* W_ih   = (const float*)d_in[5];
    const float* W_hh   = (const float*)d_in[6];
    const float* b_ih   = (const float*)d_in[7];
    const float* b_hh   = (const float*)d_in[8];
    const float* W_out  = (const float*)d_in[9];
    const float* b_out  = (const float*)d_in[10];
    float* out = (float*)d_out;

    static const int MMA_SMEM = 3840 + 32768;   // 36608 B
    cudaFuncSetAttribute(gru_mma_kernel, cudaFuncAttributeMaxDynamicSharedMemorySize, MMA_SMEM);

    prep_kernel<<<67, 256>>>(W_hh, W_ih, W_msg, b_msg);
    build_csc<<<512, 512>>>(adj);

    // t=11 writes g_h[0]; out_kernel reads g_h[0].
    for (int t = 0; t < Tt; t++) {
        agg_kernel<<<256, 256>>>(h0, t);
        gru_mma_kernel<<<512, 256, MMA_SMEM>>>(inputs, b_ih, b_hh, h0, t);
    }
    out_kernel<<<128, 256>>>(W_out, b_out, out);
}

// round 13
// speedup vs baseline: 1.4495x; 1.1732x over previous
#include <cuda_runtime.h>
#include <cuda_bf16.h>
#include <math.h>
#include <stdint.h>

#define Bb 64
#define Tt 12
#define Nn 512
#define Dd 2
#define NB (Nn*Bb)   // 32768 rows (row = node*64 + batch)

// ---------------- device scratch ----------------
__device__ float g_h[2][NB*64];          // ping-pong hidden state
__device__ float g_s[NB*64];             // s = A^T h
// B fragments (round-10 layout): [split][ktile 8][ntile 32][lane 32][reg 2]
__device__ uint32_t g_Bp[2*8*32*64];
__device__ float g_cvec[192];            // b_msg @ W_ih_m^T
__device__ float g_Wx[384];              // x weights [d][o]
__device__ float g_csum[Nn];
__device__ int   g_colj[Nn*Nn];
__device__ float g_colw[Nn*Nn];
__device__ int   g_cnt[Nn];

__device__ __forceinline__ uint32_t packbf(__nv_bfloat16 lo, __nv_bfloat16 hi) {
    return ((uint32_t)__bfloat16_as_ushort(hi) << 16) | (uint32_t)__bfloat16_as_ushort(lo);
}
__device__ __forceinline__ void split2(float v, __nv_bfloat16& b1, __nv_bfloat16& b2) {
    b1 = __float2bfloat16_rn(v);
    b2 = __float2bfloat16_rn(v - __bfloat162float(b1));
}

#define MMA16816(c, a, b) \
    asm volatile("mma.sync.aligned.m16n8k16.row.col.f32.bf16.bf16.f32 " \
        "{%0,%1,%2,%3}, {%4,%5,%6,%7}, {%8,%9}, {%0,%1,%2,%3};" \
        : "+f"((c)[0]), "+f"((c)[1]), "+f"((c)[2]), "+f"((c)[3]) \
        : "r"((a)[0]), "r"((a)[1]), "r"((a)[2]), "r"((a)[3]), \
          "r"((b)[0]), "r"((b)[1]))

// ---------------- prep: pack B fragments + tables (round-10 layout) ---------
__global__ void prep_kernel(const float* __restrict__ W_hh,
                            const float* __restrict__ W_ih,
                            const float* __restrict__ W_msg,
                            const float* __restrict__ b_msg) {
    int idx = blockIdx.x * 256 + threadIdx.x;
    if (idx < 16384) {                      // (n 0..255) x (kpair 0..63)
        int n = idx >> 6, kp = idx & 63;
        int p = n >> 6, g = n & 63;
        float w[2];
        #pragma unroll
        for (int u = 0; u < 2; u++) {
            int k = 2*kp + u;
            float v = 0.f;
            if (k < 64) {
                if (p < 3) v = W_hh[(p*64 + g)*64 + k];
            } else {
                int ks = k - 64;
                if (p != 2) {
                    int o = (p == 3) ? (128 + g) : (p*64 + g);
                    float s = 0.f;
                    for (int m = 0; m < 64; m++) s += W_msg[m*64 + ks] * W_ih[o*66 + m];
                    v = s;
                }
            }
            w[u] = v;
        }
        __nv_bfloat16 lo1, lo2, hi1, hi2;
        split2(w[0], lo1, lo2);
        split2(w[1], hi1, hi2);
        int nt = n >> 3, kt = kp >> 3, q = kp & 7;
        int lane = ((n & 7) << 2) + (q & 3);
        int reg = q >> 2;
        g_Bp[((0*8 + kt)*32 + nt)*64 + lane*2 + reg] = packbf(lo1, hi1);
        g_Bp[((1*8 + kt)*32 + nt)*64 + lane*2 + reg] = packbf(lo2, hi2);
    } else if (idx < 16384 + 384) {          // Wx[d][o]
        int j = idx - 16384;
        int d = j / 192, o = j - d*192;
        g_Wx[j] = W_ih[o*66 + 64 + d];
    } else if (idx < 16384 + 384 + 192) {    // cvec
        int o = idx - 16384 - 384;
        float s = 0.f;
        for (int m = 0; m < 64; m++) s += b_msg[m] * W_ih[o*66 + m];
        g_cvec[o] = s;
    }
}

// ---------------- deterministic CSC build + column sums (zero-padded to 64) --
__global__ void build_csc(const float* __restrict__ adj) {
    int i = blockIdx.x;
    int j = threadIdx.x;
    if (j < 64) { g_colj[i*Nn + j] = 0; g_colw[i*Nn + j] = 0.f; }
    float w = adj[j*Nn + i];
    bool p = (w > 0.f);
    unsigned mask = __ballot_sync(0xffffffffu, p);
    int warp = j >> 5, lane = j & 31;
    __shared__ int wcnt[16];
    __shared__ int wofs[16];
    __shared__ float ws[512];
    ws[j] = p ? w : 0.f;
    if (lane == 0) wcnt[warp] = __popc(mask);
    __syncthreads();
    if (j == 0) {
        int s = 0;
        for (int t = 0; t < 16; t++) { wofs[t] = s; s += wcnt[t]; }
        g_cnt[i] = s;
    }
    for (int stride = 256; stride > 0; stride >>= 1) {
        __syncthreads();
        if (j < stride) ws[j] += ws[j + stride];
    }
    if (j == 0) g_csum[i] = ws[0];
    __syncthreads();
    if (p) {
        int pos = wofs[warp] + __popc(mask & ((1u << lane) - 1u));
        g_colj[i*Nn + pos] = j;
        g_colw[i*Nn + pos] = w;
    }
}

// ---------------- per step kernel 1: s = A^T h (L1-direct, paired columns) --
// grid 512 = (bp:32) x (mc:2) x (cq:8); no smem. Warp owns 8 adjacent columns,
// processed as 4 interleaved PAIRS (both columns' 8-edge batches in flight
// together -> ~16 outstanding loads/warp). Lane = (bsub:2)x(rpair:16) float2.
struct AggAcc { float2 p[4]; };

__device__ __forceinline__ void agg_batch(const float* __restrict__ hsrc,
                                          const int* __restrict__ cj,
                                          const float* __restrict__ cw,
                                          int e, int b, int roff, AggAcc& A) {
    int4   ja = *(const int4*)(cj + e);
    int4   jb = *(const int4*)(cj + e + 4);
    float4 wa = *(const float4*)(cw + e);
    float4 wb = *(const float4*)(cw + e + 4);
    float2 h0 = *(const float2*)(hsrc + (((ja.x << 6) + b) << 6) + roff);
    float2 h1 = *(const float2*)(hsrc + (((ja.y << 6) + b) << 6) + roff);
    float2 h2 = *(const float2*)(hsrc + (((ja.z << 6) + b) << 6) + roff);
    float2 h3 = *(const float2*)(hsrc + (((ja.w << 6) + b) << 6) + roff);
    float2 h4 = *(const float2*)(hsrc + (((jb.x << 6) + b) << 6) + roff);
    float2 h5 = *(const float2*)(hsrc + (((jb.y << 6) + b) << 6) + roff);
    float2 h6 = *(const float2*)(hsrc + (((jb.z << 6) + b) << 6) + roff);
    float2 h7 = *(const float2*)(hsrc + (((jb.w << 6) + b) << 6) + roff);
    A.p[0].x += wa.x*h0.x; A.p[0].y += wa.x*h0.y;
    A.p[1].x += wa.y*h1.x; A.p[1].y += wa.y*h1.y;
    A.p[2].x += wa.z*h2.x; A.p[2].y += wa.z*h2.y;
    A.p[3].x += wa.w*h3.x; A.p[3].y += wa.w*h3.y;
    A.p[0].x += wb.x*h4.x; A.p[0].y += wb.x*h4.y;
    A.p[1].x += wb.y*h5.x; A.p[1].y += wb.y*h5.y;
    A.p[2].x += wb.z*h6.x; A.p[2].y += wb.z*h6.y;
    A.p[3].x += wb.w*h7.x; A.p[3].y += wb.w*h7.y;
}

__global__ __launch_bounds__(256)
void agg_kernel(const float* __restrict__ h0, int t) {
    const float* __restrict__ hsrc = (t == 0) ? h0 : g_h[t & 1];
    int bid = blockIdx.x;
    int bp = bid & 31, mc = (bid >> 5) & 1, cq = bid >> 6;   // cq 0..7
    int tid = threadIdx.x;
    int lane = tid & 31, wid = tid >> 5;
    int b = (bp << 1) + (lane >> 4);
    int roff = (mc << 5) + ((lane & 15) << 1);
    int colBase = (cq << 6) + (wid << 3);    // 8 columns per warp

    #pragma unroll 1
    for (int c = 0; c < 4; c++) {
        int i0 = colBase + 2*c;
        int i1 = i0 + 1;
        int cnt0 = g_cnt[i0], cnt1 = g_cnt[i1];
        const int*   cj0 = g_colj + i0*Nn;
        const float* cw0 = g_colw + i0*Nn;
        const int*   cj1 = g_colj + i1*Nn;
        const float* cw1 = g_colw + i1*Nn;
        AggAcc A0, A1;
        #pragma unroll
        for (int q = 0; q < 4; q++) { A0.p[q] = make_float2(0.f,0.f); A1.p[q] = make_float2(0.f,0.f); }

        #pragma unroll 2
        for (int u = 0; u < 4; u++) {
            agg_batch(hsrc, cj0, cw0, u*8, b, roff, A0);
            agg_batch(hsrc, cj1, cw1, u*8, b, roff, A1);
        }
        if (cnt0 > 32) {
            #pragma unroll 2
            for (int u = 4; u < 8; u++) agg_batch(hsrc, cj0, cw0, u*8, b, roff, A0);
            for (int e = 64; e < cnt0; e++) {
                float2 hv = *(const float2*)(hsrc + (((cj0[e] << 6) + b) << 6) + roff);
                A0.p[0].x += cw0[e]*hv.x; A0.p[0].y += cw0[e]*hv.y;
            }
        }
        if (cnt1 > 32) {
            #pragma unroll 2
            for (int u = 4; u < 8; u++) agg_batch(hsrc, cj1, cw1, u*8, b, roff, A1);
            for (int e = 64; e < cnt1; e++) {
                float2 hv = *(const float2*)(hsrc + (((cj1[e] << 6) + b) << 6) + roff);
                A1.p[0].x += cw1[e]*hv.x; A1.p[0].y += cw1[e]*hv.y;
            }
        }
        float2 r0, r1;
        r0.x = (A0.p[0].x + A0.p[1].x) + (A0.p[2].x + A0.p[3].x);
        r0.y = (A0.p[0].y + A0.p[1].y) + (A0.p[2].y + A0.p[3].y);
        r1.x = (A1.p[0].x + A1.p[1].x) + (A1.p[2].x + A1.p[3].x);
        r1.y = (A1.p[0].y + A1.p[1].y) + (A1.p[2].y + A1.p[3].y);
        *(float2*)(g_s + (((i0 << 6) + b) << 6) + roff) = r0;
        *(float2*)(g_s + (((i1 << 6) + b) << 6) + roff) = r1;
    }
}

// ---------------- per step kernel 2: HMMA GEMM + in-register GRU epilogue ----
// (exact round-10/12 version: strided N-tiles, uint2 B loads, double-buffered)
__global__ __launch_bounds__(256, 2)
void gru_mma_kernel(const float* __restrict__ inputs,
                    const float* __restrict__ b_ih,
                    const float* __restrict__ b_hh,
                    const float* __restrict__ h0,
                    int t) {
    extern __shared__ char smc[];
    float* tb = (float*)smc;                       // 960 floats
    uint32_t* apack = (uint32_t*)(smc + 3840);     // [s][mt4][kt8][lane32][reg4] = 32KB

    const float* __restrict__ hsrc = (t == 0) ? h0 : g_h[t & 1];
    float* __restrict__ hdst = g_h[(t + 1) & 1];

    int n = blockIdx.x;
    int rowBase = n << 6;
    int tid = threadIdx.x;

    for (int idx = tid; idx < 960; idx += 256) {
        float v = (idx < 192) ? b_ih[idx]
                : (idx < 384) ? b_hh[idx - 192]
                : (idx < 576) ? g_cvec[idx - 384]
                : g_Wx[idx - 576];
        tb[idx] = v;
    }
    for (int it = 0; it < 16; it++) {
        int item = tid + it*256;            // (r 0..63) x (kp 0..63)
        int r = item >> 6, kp = item & 63;
        int rowg = rowBase + r;
        const float* src = (kp < 32) ? (hsrc + rowg*64 + 2*kp)
                                     : (g_s + rowg*64 + 2*kp - 64);
        float2 v = *(const float2*)src;
        __nv_bfloat16 lo1, lo2, hi1, hi2;
        split2(v.x, lo1, lo2);
        split2(v.y, hi1, hi2);
        int mt = r >> 4, kt = kp >> 3, q = kp & 7;
        int lane = ((r & 7) << 2) + (q & 3);
        int reg = ((q >> 2) << 1) + ((r & 15) >> 3);
        apack[((0*4 + mt)*8 + kt)*128 + lane*4 + reg] = packbf(lo1, hi1);
        apack[((1*4 + mt)*8 + kt)*128 + lane*4 + reg] = packbf(lo2, hi2);
    }
    __syncthreads();

    int lane = tid & 31;
    int w = tid >> 5;
    int mw = w & 1, nw = w >> 1;

    float c[2][8][4];
    #pragma unroll
    for (int i = 0; i < 2; i++)
        #pragma unroll
        for (int j = 0; j < 8; j++)
            #pragma unroll
            for (int q = 0; q < 4; q++) c[i][j][q] = 0.f;

    const uint32_t* __restrict__ Bp = g_Bp;
    uint32_t bbuf[2][8][2];
    {
        const uint32_t* bp = Bp + lane*2;
        #pragma unroll
        for (int j = 0; j < 8; j++)
            *(uint2*)bbuf[0][j] = *(const uint2*)(bp + (4*j + nw)*64);
    }
    #pragma unroll 2
    for (int bi = 0; bi < 24; bi++) {
        int par = bi & 1;
        if (bi < 23) {
            int bn = bi + 1;
            int cn = bn >> 3, ktn = bn & 7;
            int sbn = (cn == 2) ? 1 : 0;
            const uint32_t* bp = Bp + ((sbn*8 + ktn)*32)*64 + lane*2;
            #pragma unroll
            for (int j = 0; j < 8; j++)
                *(uint2*)bbuf[par ^ 1][j] = *(const uint2*)(bp + (4*j + nw)*64);
        }
        int combo = bi >> 3, kt = bi & 7;
        int sa = (combo == 1) ? 1 : 0;
        uint32_t a[2][4];
        #pragma unroll
        for (int mt2 = 0; mt2 < 2; mt2++)
            *(uint4*)a[mt2] = *(const uint4*)(apack +
                ((sa*4 + mw*2 + mt2)*8 + kt)*128 + lane*4);
        #pragma unroll
        for (int j = 0; j < 8; j++) {
            MMA16816(c[0][j], a[0], bbuf[par][j]);
            MMA16816(c[1][j], a[1], bbuf[par][j]);
        }
    }

    float cs = g_csum[n];
    int g4 = lane >> 2, tg = lane & 3;
    #pragma unroll
    for (int mt2 = 0; mt2 < 2; mt2++) {
        #pragma unroll
        for (int qh = 0; qh < 2; qh++) {
            int row = mw*32 + mt2*16 + g4 + 8*qh;
            int rowg = rowBase + row;
            const float* xp = inputs + ((row*Tt + t)*Nn + n)*Dd;
            float x0 = xp[0], x1 = xp[1];
            #pragma unroll
            for (int jg = 0; jg < 2; jg++) {
                int g0 = jg*32 + nw*8 + tg*2;
                float2 hold = *(const float2*)(hsrc + rowg*64 + g0);
                float hn[2];
                #pragma unroll
                for (int u = 0; u < 2; u++) {
                    int g = g0 + u;
                    int q = qh*2 + u;
                    float vr  = c[mt2][0*2 + jg][q] + tb[g]       + tb[192 + g]
                              + cs*tb[384 + g] + x0*tb[576 + g] + x1*tb[768 + g];
                    float vz  = c[mt2][1*2 + jg][q] + tb[64 + g]  + tb[256 + g]
                              + cs*tb[448 + g] + x0*tb[640 + g] + x1*tb[832 + g];
                    float vnh = c[mt2][2*2 + jg][q] + tb[320 + g];
                    float vns = c[mt2][3*2 + jg][q] + tb[128 + g]
                              + cs*tb[512 + g] + x0*tb[704 + g] + x1*tb[896 + g];
                    float rg = 1.f / (1.f + expf(-vr));
                    float zg = 1.f / (1.f + expf(-vz));
                    float nn = tanhf(vns + rg*vnh);
                    hn[u] = (1.f - zg)*nn + zg*((u == 0) ? hold.x : hold.y);
                }
                *(float2*)(hdst + rowg*64 + g0) = make_float2(hn[0], hn[1]);
            }
        }
    }
}

// ---------------- final readout ----------------
__global__ void out_kernel(const float* __restrict__ W_out,
                           const float* __restrict__ b_out,
                           float* __restrict__ out) {
    __shared__ float wo[12*64];
    __shared__ float bo[12];
    int tid = threadIdx.x;
    for (int idx = tid; idx < 768; idx += 256) wo[idx] = W_out[idx];
    if (tid < 12) bo[tid] = b_out[tid];
    __syncthreads();
    int row = blockIdx.x * 256 + tid;
    float accs[12];
    #pragma unroll
    for (int hh = 0; hh < 12; hh++) accs[hh] = bo[hh];
    for (int k = 0; k < 64; k++) {
        float hv = g_h[0][row*64 + k];
        #pragma unroll
        for (int hh = 0; hh < 12; hh++) accs[hh] += hv * wo[hh*64 + k];
    }
    int n = row >> 6, b = row & 63;
    #pragma unroll
    for (int hh = 0; hh < 12; hh++)
        out[(b*12 + hh)*512 + n] = accs[hh];
}

extern "C" void kernel_launch(void* const* d_in, const int* in_sizes, int n_in,
                              void* d_out, int out_size) {
    const float* inputs = (const float*)d_in[0];
    const float* h0     = (const float*)d_in[1];
    const float* adj    = (const float*)d_in[2];
    const float* W_msg  = (const float*)d_in[3];
    const float* b_msg  = (const float*)d_in[4];
    const float* W_ih   = (const float*)d_in[5];
    const float* W_hh   = (const float*)d_in[6];
    const float* b_ih   = (const float*)d_in[7];
    const float* b_hh   = (const float*)d_in[8];
    const float* W_out  = (const float*)d_in[9];
    const float* b_out  = (const float*)d_in[10];
    float* out = (float*)d_out;

    static const int MMA_SMEM = 3840 + 32768;   // 36608 B
    cudaFuncSetAttribute(gru_mma_kernel, cudaFuncAttributeMaxDynamicSharedMemorySize, MMA_SMEM);

    prep_kernel<<<67, 256>>>(W_hh, W_ih, W_msg, b_msg);
    build_csc<<<512, 512>>>(adj);

    // t=11 writes g_h[0]; out_kernel reads g_h[0].
    for (int t = 0; t < Tt; t++) {
        agg_kernel<<<512, 256>>>(h0, t);
        gru_mma_kernel<<<512, 256, MMA_SMEM>>>(inputs, b_ih, b_hh, h0, t);
    }
    out_kernel<<<128, 256>>>(W_out, b_out, out);
}